// round 3
// baseline (speedup 1.0000x reference)
#include <cuda_runtime.h>
#include <cuda_bf16.h>
#include <cstdint>

// Problem constants (AttentionLayer: N=4, S=T=2048, D=1024)
#define NB 4
#define SQ 2048
#define TK 2048
#define DD 1024

// Scratch (allocation-free rule: __device__ globals)
static __device__ float g_q[NB * SQ * DD];                 // 33.5 MB
static __device__ float g_k[NB * TK * DD];                 // 33.5 MB
static __device__ float g_v[NB * TK * DD];                 // 33.5 MB
static __device__ float g_s[(size_t)NB * SQ * TK];         // 64 MB scores/probs

// ---------------------------------------------------------------------------
// TF32 helpers: split fp32 into hi (tf32) + lo (tf32 of residual).
// 3 MMAs per atom (hi*hi + lo*hi + hi*lo) gives ~2^-21 accuracy (~fp32).
// ---------------------------------------------------------------------------
__device__ __forceinline__ uint32_t f2tf32(float x) {
    uint32_t r;
    asm("cvt.rna.tf32.f32 %0, %1;" : "=r"(r) : "f"(x));
    return r;
}
__device__ __forceinline__ void tf32_split(float x, uint32_t& h, uint32_t& l) {
    h = f2tf32(x);
    l = f2tf32(x - __uint_as_float(h));
}

#define MMA_TF32(c, a, b)                                              \
    asm volatile(                                                      \
        "mma.sync.aligned.m16n8k8.row.col.f32.tf32.tf32.f32 "          \
        "{%0,%1,%2,%3}, {%4,%5,%6,%7}, {%8,%9}, {%0,%1,%2,%3};"        \
        : "+f"(c[0]), "+f"(c[1]), "+f"(c[2]), "+f"(c[3])               \
        : "r"(a[0]), "r"(a[1]), "r"(a[2]), "r"(a[3]),                  \
          "r"(b[0]), "r"(b[1]))

// ---------------------------------------------------------------------------
// Warp-tile compute over one 128x128x16 smem tile.
// Smem layout: As[k][m], Bs[k][n]. 8 warps: warp_m in {0,1}, warp_n in {0..3};
// warp tile 64(m) x 32(n) = 4x4 m16n8k8 atoms.
// ---------------------------------------------------------------------------
__device__ __forceinline__ void mma_tile_compute(
    const float (*__restrict__ As)[132], const float (*__restrict__ Bs)[132],
    float acc[4][4][4], int warp_m, int warp_n, int lane)
{
    const int g  = lane >> 2;   // 0..7
    const int t4 = lane & 3;    // 0..3

    #pragma unroll
    for (int k8 = 0; k8 < 16; k8 += 8) {
        uint32_t ah[4][4], al[4][4];
        #pragma unroll
        for (int i = 0; i < 4; i++) {
            const int mb = warp_m * 64 + i * 16;
            tf32_split(As[k8 + t4][mb + g],         ah[i][0], al[i][0]);
            tf32_split(As[k8 + t4][mb + g + 8],     ah[i][1], al[i][1]);
            tf32_split(As[k8 + t4 + 4][mb + g],     ah[i][2], al[i][2]);
            tf32_split(As[k8 + t4 + 4][mb + g + 8], ah[i][3], al[i][3]);
        }
        uint32_t bh[4][2], bl[4][2];
        #pragma unroll
        for (int j = 0; j < 4; j++) {
            const int nb = warp_n * 32 + j * 8;
            tf32_split(Bs[k8 + t4][nb + g],     bh[j][0], bl[j][0]);
            tf32_split(Bs[k8 + t4 + 4][nb + g], bh[j][1], bl[j][1]);
        }
        #pragma unroll
        for (int i = 0; i < 4; i++)
            #pragma unroll
            for (int j = 0; j < 4; j++) {
                MMA_TF32(acc[i][j], al[i], bh[j]);  // small terms first
                MMA_TF32(acc[i][j], ah[i], bl[j]);
                MMA_TF32(acc[i][j], ah[i], bh[j]);
            }
    }
}

// Store the warp's accumulators: D[m][n] layout of m16n8k8 (c0,c1 row g;
// c2,c3 row g+8; cols t4*2, t4*2+1).
__device__ __forceinline__ void mma_tile_store(
    float* __restrict__ C, int ldc, int m0, int n0,
    float acc[4][4][4], int warp_m, int warp_n, int lane, float scale)
{
    const int g  = lane >> 2;
    const int t4 = lane & 3;
    #pragma unroll
    for (int i = 0; i < 4; i++) {
        #pragma unroll
        for (int j = 0; j < 4; j++) {
            const int r0 = m0 + warp_m * 64 + i * 16 + g;
            const int c0 = n0 + warp_n * 32 + j * 8 + t4 * 2;
            float2 lo = make_float2(acc[i][j][0] * scale, acc[i][j][1] * scale);
            float2 hi = make_float2(acc[i][j][2] * scale, acc[i][j][3] * scale);
            *(float2*)(C + (size_t)r0 * ldc + c0)       = lo;
            *(float2*)(C + (size_t)(r0 + 8) * ldc + c0) = hi;
        }
    }
}

// ---------------------------------------------------------------------------
// GEMM (both operands K-major): C[m][n] = scale * sum_k A[m][k]*B[n][k]
// 256 threads, 128x128 tile, k-chunk 16.
// ---------------------------------------------------------------------------
__device__ __forceinline__ void gemm128_kk_mma(
    const float* __restrict__ A, const float* __restrict__ B, float* __restrict__ C,
    int lda, int ldb, int ldc, int K, int m0, int n0, float scale)
{
    __shared__ float As[16][132];
    __shared__ float Bs[16][132];

    const int tid    = threadIdx.x;
    const int lane   = tid & 31;
    const int wid    = tid >> 5;
    const int warp_m = wid & 1;
    const int warp_n = wid >> 1;
    const int lr     = tid >> 2;        // 0..63 loader row
    const int lk     = (tid & 3) << 2;  // 0,4,8,12 loader k offset

    float acc[4][4][4] = {};

    const float* Ap0 = A + (size_t)(m0 + lr)      * lda + lk;
    const float* Ap1 = A + (size_t)(m0 + 64 + lr) * lda + lk;
    const float* Bp0 = B + (size_t)(n0 + lr)      * ldb + lk;
    const float* Bp1 = B + (size_t)(n0 + 64 + lr) * ldb + lk;

    for (int k0 = 0; k0 < K; k0 += 16) {
        float4 a0 = *(const float4*)(Ap0 + k0);
        float4 a1 = *(const float4*)(Ap1 + k0);
        float4 b0 = *(const float4*)(Bp0 + k0);
        float4 b1 = *(const float4*)(Bp1 + k0);

        __syncthreads();
        As[lk + 0][lr] = a0.x; As[lk + 1][lr] = a0.y;
        As[lk + 2][lr] = a0.z; As[lk + 3][lr] = a0.w;
        As[lk + 0][64 + lr] = a1.x; As[lk + 1][64 + lr] = a1.y;
        As[lk + 2][64 + lr] = a1.z; As[lk + 3][64 + lr] = a1.w;
        Bs[lk + 0][lr] = b0.x; Bs[lk + 1][lr] = b0.y;
        Bs[lk + 2][lr] = b0.z; Bs[lk + 3][lr] = b0.w;
        Bs[lk + 0][64 + lr] = b1.x; Bs[lk + 1][64 + lr] = b1.y;
        Bs[lk + 2][64 + lr] = b1.z; Bs[lk + 3][64 + lr] = b1.w;
        __syncthreads();

        mma_tile_compute(As, Bs, acc, warp_m, warp_n, lane);
    }
    mma_tile_store(C, ldc, m0, n0, acc, warp_m, warp_n, lane, scale);
}

// ---------------------------------------------------------------------------
// Kernel 1: Q/K/V projections. y = x @ W^T (W row-major [out,in] => K-major)
// ---------------------------------------------------------------------------
__global__ void __launch_bounds__(256)
proj_kernel(const float* __restrict__ q, const float* __restrict__ k,
            const float* __restrict__ v, const float* __restrict__ wq,
            const float* __restrict__ wk, const float* __restrict__ wv)
{
    const float* X; const float* W; float* Y;
    if (blockIdx.z == 0)      { X = q; W = wq; Y = g_q; }
    else if (blockIdx.z == 1) { X = k; W = wk; Y = g_k; }
    else                      { X = v; W = wv; Y = g_v; }
    gemm128_kk_mma(X, W, Y, DD, DD, DD, DD, blockIdx.y * 128, blockIdx.x * 128, 1.0f);
}

// ---------------------------------------------------------------------------
// Kernel 2: logits S = (q @ k^T) / sqrt(D); skip tiles above causal diagonal.
// ---------------------------------------------------------------------------
__global__ void __launch_bounds__(256)
scores_kernel()
{
    const int m0 = blockIdx.y * 128;
    const int n0 = blockIdx.x * 128;
    if (n0 > m0) return;               // fully masked tile
    const int n = blockIdx.z;
    gemm128_kk_mma(g_q + (size_t)n * SQ * DD,
                   g_k + (size_t)n * TK * DD,
                   g_s + (size_t)n * SQ * TK,
                   DD, DD, TK, DD, m0, n0, 0.03125f /* 1/sqrt(1024) */);
}

// ---------------------------------------------------------------------------
// Kernel 3: causal row softmax in place; zeros above the diagonal (also in
// tiles scores_kernel skipped), so PV can read whole tiles.
// ---------------------------------------------------------------------------
__global__ void __launch_bounds__(256)
softmax_kernel()
{
    __shared__ float red[8];
    const int row = blockIdx.x;             // 0 .. NB*SQ-1
    const int s   = row & (SQ - 1);
    const int len = s + 1;
    float* x = g_s + (size_t)row * TK;
    const int tid = threadIdx.x;

    float vals[TK / 256];
    float m = -3.0e38f;
    #pragma unroll
    for (int i = 0; i < TK / 256; i++) {
        int j = tid + i * 256;
        vals[i] = (j < len) ? x[j] : -3.0e38f;
        m = fmaxf(m, vals[i]);
    }
    #pragma unroll
    for (int o = 16; o; o >>= 1) m = fmaxf(m, __shfl_xor_sync(0xffffffffu, m, o));
    if ((tid & 31) == 0) red[tid >> 5] = m;
    __syncthreads();
    m = red[0];
    #pragma unroll
    for (int w = 1; w < 8; w++) m = fmaxf(m, red[w]);
    __syncthreads();

    float sum = 0.f;
    #pragma unroll
    for (int i = 0; i < TK / 256; i++) {
        int j = tid + i * 256;
        float e = (j < len) ? expf(vals[i] - m) : 0.f;
        vals[i] = e;
        sum += e;
    }
    #pragma unroll
    for (int o = 16; o; o >>= 1) sum += __shfl_xor_sync(0xffffffffu, sum, o);
    if ((tid & 31) == 0) red[tid >> 5] = sum;
    __syncthreads();
    float tot = red[0];
    #pragma unroll
    for (int w = 1; w < 8; w++) tot += red[w];
    const float inv = 1.0f / tot;

    #pragma unroll
    for (int i = 0; i < TK / 256; i++) {
        int j = tid + i * 256;
        x[j] = vals[i] * inv;
    }
}

// ---------------------------------------------------------------------------
// Kernel 4: O = P @ V. A=[SQ,TK] K-major, V=[TK,DD] N-major loader.
// K-loop stops at m0+128 (probs beyond are exactly 0).
// ---------------------------------------------------------------------------
__global__ void __launch_bounds__(256)
pv_kernel(float* __restrict__ out)
{
    __shared__ float As[16][132];
    __shared__ float Bs[16][132];

    const int n  = blockIdx.z;
    const int m0 = blockIdx.y * 128;
    const int n0 = blockIdx.x * 128;
    const float* A = g_s + (size_t)n * SQ * TK;
    const float* B = g_v + (size_t)n * TK * DD;
    float*       C = out + (size_t)n * SQ * DD;
    const int Kend = m0 + 128;

    const int tid    = threadIdx.x;
    const int lane   = tid & 31;
    const int wid    = tid >> 5;
    const int warp_m = wid & 1;
    const int warp_n = wid >> 1;
    const int lr     = tid >> 2;
    const int lk     = (tid & 3) << 2;
    const int br     = tid >> 5;         // 0..7
    const int bc     = (tid & 31) << 2;  // 0..124

    float acc[4][4][4] = {};

    for (int k0 = 0; k0 < Kend; k0 += 16) {
        float4 a0 = *(const float4*)(A + (size_t)(m0 + lr)      * TK + k0 + lk);
        float4 a1 = *(const float4*)(A + (size_t)(m0 + 64 + lr) * TK + k0 + lk);
        float4 v0 = *(const float4*)(B + (size_t)(k0 + br)     * DD + n0 + bc);
        float4 v1 = *(const float4*)(B + (size_t)(k0 + 8 + br) * DD + n0 + bc);

        __syncthreads();
        As[lk + 0][lr] = a0.x; As[lk + 1][lr] = a0.y;
        As[lk + 2][lr] = a0.z; As[lk + 3][lr] = a0.w;
        As[lk + 0][64 + lr] = a1.x; As[lk + 1][64 + lr] = a1.y;
        As[lk + 2][64 + lr] = a1.z; As[lk + 3][64 + lr] = a1.w;
        *(float4*)&Bs[br][bc]     = v0;
        *(float4*)&Bs[br + 8][bc] = v1;
        __syncthreads();

        mma_tile_compute(As, Bs, acc, warp_m, warp_n, lane);
    }
    mma_tile_store(C, DD, m0, n0, acc, warp_m, warp_n, lane, 1.0f);
}

// ---------------------------------------------------------------------------
// Inputs (metadata order): query, key, value, attn_mask (int32 tril — causal
// by construction, handled analytically), Wq, Wk, Wv. Output fp32 [4,2048,1024].
// ---------------------------------------------------------------------------
extern "C" void kernel_launch(void* const* d_in, const int* in_sizes, int n_in,
                              void* d_out, int out_size)
{
    const float* q  = (const float*)d_in[0];
    const float* k  = (const float*)d_in[1];
    const float* v  = (const float*)d_in[2];
    const float* wq = (const float*)d_in[4];
    const float* wk = (const float*)d_in[5];
    const float* wv = (const float*)d_in[6];
    float* out = (float*)d_out;

    proj_kernel<<<dim3(DD / 128, (NB * SQ) / 128, 3), 256>>>(q, k, v, wq, wk, wv);
    scores_kernel<<<dim3(TK / 128, SQ / 128, NB), 256>>>();
    softmax_kernel<<<dim3(NB * SQ), 256>>>();
    pv_kernel<<<dim3(DD / 128, SQ / 128, NB), 256>>>(out);
}